// round 5
// baseline (speedup 1.0000x reference)
#include <cuda_runtime.h>
#include <math.h>

#define NTOK 1568
#define CH 32
#define NPIX 256
#define NEXP 8
#define CAPN 245
#define NCLS 1000
#define HWD 224
#define HP 14
#define EPSV 1e-5f
#define PI_F 3.14159265358979323846f

typedef unsigned long long u64;

// ---- scratch (no allocations allowed) ----
__device__ float g_tokens[NTOK * CH * NPIX];   // token layout (n,c,py,px)
__device__ float g_cmean[NTOK * CH];
__device__ int   g_top1[NTOK];
__device__ float g_ptop[NTOK];
__device__ float g_lse[NTOK];
__device__ float g_probs[NTOK * NEXP];
__device__ float g_wn[NTOK];
__device__ float g_psum[NTOK * CH];
__device__ float g_psumsq[NTOK * CH];
// duplicated expert weights: [e][co][ci][ky][4] u64 {w,w} (slot 3 = 0)
__device__ __align__(16) u64 g_wdup[NEXP * CH * CH * 12];

// ---- f32x2 helpers (Blackwell packed fp32; ptxas never auto-fuses) ----
__device__ __forceinline__ u64 pack2(float x, float y) {
    u64 r; asm("mov.b64 %0, {%1, %2};" : "=l"(r) : "f"(x), "f"(y)); return r;
}
__device__ __forceinline__ void unpack2(u64 v, float& x, float& y) {
    asm("mov.b64 {%0, %1}, %2;" : "=f"(x), "=f"(y) : "l"(v));
}
__device__ __forceinline__ u64 ffma2(u64 a, u64 b, u64 c) {
    u64 d; asm("fma.rn.f32x2 %0, %1, %2, %3;" : "=l"(d) : "l"(a), "l"(b), "l"(c));
    return d;
}

// ============================================================
// K0: duplicate expert weights into {w,w} u64 pairs (ky-padded)
// ============================================================
__global__ void __launch_bounds__(1024)
k0_wdup(const float* __restrict__ EW) {
    int i = blockIdx.x * 1024 + threadIdx.x;        // over 8*32*32*12
    if (i >= NEXP * CH * CH * 12) return;
    int kx = i & 3;
    int rest = i >> 2;
    int ky = rest % 3;
    int cc = rest / 3;                               // (e*32+co)*32+ci
    float w = (kx < 3) ? EW[cc * 9 + ky * 3 + kx] : 0.f;
    g_wdup[cc * 12 + ky * 4 + kx] = pack2(w, w);
}

// ============================================================
// K1: stem conv3x3 (3->32) + BN + SiLU -> tokens; fused channel means
// ============================================================
__global__ void __launch_bounds__(256)
k1_stem(const float* __restrict__ X, const float* __restrict__ W,
        const float* __restrict__ bnw, const float* __restrict__ bnb) {
    __shared__ __align__(16) float sIn[3 * 18 * 18];
    __shared__ __align__(16) float sW[32 * 28];   // padded to 28/row for b64 pairs
    __shared__ float sBw[32], sBb[32];
    __shared__ float sPart[8 * 32];
    int n = blockIdx.x;
    int b = n / 196, pr = (n % 196) / HP, pc = n % HP;
    int tid = threadIdx.x;

    for (int i = tid; i < 3 * 18 * 18; i += 256) {
        int ci = i / 324, r = (i % 324) / 18, c = i % 18;
        int gy = pr * 16 + r - 1, gx = pc * 16 + c - 1;
        float v = 0.f;
        if (gy >= 0 && gy < HWD && gx >= 0 && gx < HWD)
            v = X[((b * 3 + ci) * HWD + gy) * HWD + gx];
        sIn[i] = v;
    }
    for (int i = tid; i < 32 * 28; i += 256) {
        int co = i / 28, k = i % 28;
        sW[i] = (k < 27) ? W[co * 27 + k] : 0.f;
    }
    if (tid < 32) { sBw[tid] = bnw[tid]; sBb[tid] = bnb[tid]; }
    __syncthreads();

    int py = tid >> 4, px = tid & 15;
    float xin[28];
#pragma unroll
    for (int ci = 0; ci < 3; ci++)
#pragma unroll
        for (int dy = 0; dy < 3; dy++)
#pragma unroll
            for (int dx = 0; dx < 3; dx++)
                xin[ci * 9 + dy * 3 + dx] = sIn[ci * 324 + (py + dy) * 18 + (px + dx)];
    xin[27] = 0.f;
    u64 xp[14];
#pragma unroll
    for (int j = 0; j < 14; j++) xp[j] = pack2(xin[2 * j], xin[2 * j + 1]);

    int lane = tid & 31, wid = tid >> 5;
    for (int co = 0; co < 32; co++) {
        u64 acc = 0ULL;
#pragma unroll
        for (int j = 0; j < 14; j++)
            acc = ffma2(*(const u64*)(sW + co * 28 + 2 * j), xp[j], acc);
        float a0, a1; unpack2(acc, a0, a1);
        float a = a0 + a1;
        a = a * sBw[co] + sBb[co];
        float s = a / (1.f + __expf(-a));
        g_tokens[(n * CH + co) * NPIX + tid] = s;
        float ws = s;
#pragma unroll
        for (int off = 16; off > 0; off >>= 1)
            ws += __shfl_down_sync(0xffffffffu, ws, off);
        if (lane == 0) sPart[wid * 32 + co] = ws;
    }
    __syncthreads();
    if (tid < 32) {
        float sum = 0.f;
#pragma unroll
        for (int w = 0; w < 8; w++) sum += sPart[w * 32 + tid];
        g_cmean[n * CH + tid] = sum * (1.f / 256.f);
    }
}

// ============================================================
// K2: gate — one thread per token. 13 blocks x 128 threads.
// ============================================================
__global__ void __launch_bounds__(128)
k2_gate(const float* __restrict__ gate_w, const float* __restrict__ gate_b) {
    __shared__ float sGw[50 * 8];
    __shared__ float sGb[8];
    __shared__ float tab[14][9];
    int tid = threadIdx.x;

    for (int i = tid; i < 400; i += 128) sGw[i] = gate_w[i];
    if (tid < 8) sGb[tid] = gate_b[tid];
    if (tid < 56) {
        int b2 = tid >> 2, k = tid & 3;
        float f = (float)(1 << k) * PI_F;
        float ss = 0.f, cs = 0.f;
        for (int r = 0; r < 16; r++) {
            float ang = f * ((16.f * b2 + (float)r + 0.5f) / 224.f);
            ss += sinf(ang); cs += cosf(ang);
        }
        tab[b2][1 + 2 * k] = ss * (1.f / 16.f);
        tab[b2][2 + 2 * k] = cs * (1.f / 16.f);
    } else if (tid < 70) {
        int b2 = tid - 56;
        tab[b2][0] = (16.f * b2 + 8.f) / 224.f;
    }
    __syncthreads();

    int n = blockIdx.x * 128 + tid;
    if (n >= NTOK) return;
    int pr = (n % 196) / HP, pc = n % HP;

    float l[8];
#pragma unroll
    for (int e = 0; e < 8; e++) l[e] = sGb[e];
    const float4* cm4 = (const float4*)&g_cmean[n * CH];
#pragma unroll
    for (int i4 = 0; i4 < 8; i4++) {
        float4 v4 = cm4[i4];
        float vv[4] = {v4.x, v4.y, v4.z, v4.w};
#pragma unroll
        for (int q = 0; q < 4; q++) {
            int i = i4 * 4 + q;
#pragma unroll
            for (int e = 0; e < 8; e++) l[e] = fmaf(vv[q], sGw[i * 8 + e], l[e]);
        }
    }
    {
        float v0 = tab[pr][0], v1 = tab[pc][0];
#pragma unroll
        for (int e = 0; e < 8; e++) {
            l[e] = fmaf(v0, sGw[32 * 8 + e], l[e]);
            l[e] = fmaf(v1, sGw[33 * 8 + e], l[e]);
        }
    }
#pragma unroll
    for (int k = 0; k < 4; k++) {
#pragma unroll
        for (int sub = 0; sub < 4; sub++) {
            float v = (sub < 2) ? tab[pr][1 + 2 * k + sub] : tab[pc][1 + 2 * k + (sub - 2)];
#pragma unroll
            for (int e = 0; e < 8; e++)
                l[e] = fmaf(v, sGw[(34 + 4 * k + sub) * 8 + e], l[e]);
        }
    }
    float mx = l[0]; int am = 0;
#pragma unroll
    for (int e = 1; e < 8; e++) if (l[e] > mx) { mx = l[e]; am = e; }
    float pe[8], se = 0.f;
#pragma unroll
    for (int e = 0; e < 8; e++) { pe[e] = __expf(l[e] - mx); se += pe[e]; }
    float inv = 1.f / se;
#pragma unroll
    for (int e = 0; e < 8; e++) g_probs[n * 8 + e] = pe[e] * inv;
    g_top1[n] = am;
    g_ptop[n] = pe[am] * inv;
    g_lse[n] = mx + __logf(se);
}

// ============================================================
// K3: capacity scan (ballot, exact token order) + loss reductions
// ============================================================
__global__ void __launch_bounds__(512)
k3_dispatch(float* __restrict__ d_out) {
    __shared__ int   sT[NTOK];
    __shared__ float sbuf[512];
    __shared__ float sres[17];
    __shared__ int   sWC[16 * 9];
    __shared__ int   sRun[8];
    int tid = threadIdx.x;

    for (int i = tid; i < NTOK; i += 512) sT[i] = g_top1[i];
    if (tid < 8) sRun[tid] = 0;
    if (tid < 144) sWC[tid] = 0;
    __syncthreads();

    float part[17];
#pragma unroll
    for (int q = 0; q < 17; q++) part[q] = 0.f;
    for (int n = tid; n < NTOK; n += 512) {
        float lse = g_lse[n];
        part[0] += lse * lse;
        const float4* p4 = (const float4*)&g_probs[n * 8];
        float4 a = p4[0], b = p4[1];
        part[1] += a.x; part[2] += a.y; part[3] += a.z; part[4] += a.w;
        part[5] += b.x; part[6] += b.y; part[7] += b.z; part[8] += b.w;
        part[9 + sT[n]] += 1.f;
    }

    int lane = tid & 31, wid = tid >> 5;
    for (int c = 0; c < 4; c++) {
        int n = c * 512 + tid;
        bool act = n < NTOK;
        int e = act ? sT[n] : 8;
        unsigned m = __match_any_sync(0xffffffffu, e);
        int lr = __popc(m & ((1u << lane) - 1u));
        if (lr == 0) sWC[wid * 9 + e] = __popc(m);
        __syncthreads();
        if (act) {
            int base = sRun[e];
            for (int w2 = 0; w2 < wid; w2++) base += sWC[w2 * 9 + e];
            int rank = base + lr;
            g_wn[n] = (rank < CAPN) ? g_ptop[n] : 0.f;
        }
        int s = 0;
        if (tid < 8) for (int w2 = 0; w2 < 16; w2++) s += sWC[w2 * 9 + tid];
        __syncthreads();
        if (tid < 8) sRun[tid] += s;
        if (tid < 144) sWC[tid] = 0;
        __syncthreads();
    }

    for (int q = 0; q < 17; q++) {
        sbuf[tid] = part[q];
        __syncthreads();
        for (int s2 = 256; s2 > 0; s2 >>= 1) {
            if (tid < s2) sbuf[tid] += sbuf[tid + s2];
            __syncthreads();
        }
        if (tid == 0) sres[q] = sbuf[0];
        __syncthreads();
    }
    if (tid == 0) {
        float z = sres[0] / (float)NTOK;
        float imb = 0.f;
        for (int e = 0; e < 8; e++) imb += sres[1 + e] * sres[9 + e];
        imb *= (float)NEXP / ((float)NTOK * (float)NTOK);
        d_out[8000] = z;
        d_out[8001] = imb;
    }
}

// ============================================================
// K4: expert conv3x3 (32->32) + SiLU + combine.
// f32x2 math with zero operand-marshalling:
//  - weights pre-duplicated {w,w} in g_wdup (LDG.128 broadcast)
//  - odd pixel pairs from a shifted smem copy (aligned LDS.64)
// ============================================================
#define SX_ELEMS  (CH * 324)          // 18x18 padded, stride 18
#define SXO_ELEMS (CH * 360)          // 18 rows x stride 20, cols 0..15 valid
#define SMEM_K4   ((SX_ELEMS + SXO_ELEMS) * 4)

__global__ void __launch_bounds__(256, 2)
k4_expert(const float* __restrict__ EB, const float* __restrict__ gamma) {
    extern __shared__ __align__(16) float smem[];
    float* sX  = smem;                 // [c][18][18], pixel (r,x) at [r+1][x+1]
    float* sXo = smem + SX_ELEMS;      // [c][18][20], sXo[r][j] = sX[r][j+1]
    int n = blockIdx.x;
    int tid = threadIdx.x;
    float wn = g_wn[n];
    int e = g_top1[n];

    {
        u64* z = (u64*)smem;
        for (int i = tid; i < (SX_ELEMS + SXO_ELEMS) / 2; i += 256) z[i] = 0ULL;
    }
    __syncthreads();
    const float4* src = (const float4*)(g_tokens + (size_t)n * CH * NPIX);
    for (int i = tid; i < CH * NPIX / 4; i += 256) {
        float4 v = src[i];
        int c = i >> 6;
        int p = (i & 63) * 4;
        int pr = p >> 4, px = p & 15;
        float* d1 = sX + c * 324 + (pr + 1) * 18 + px + 1;
        d1[0] = v.x; d1[1] = v.y; d1[2] = v.z; d1[3] = v.w;
        *(float4*)(sXo + c * 360 + (pr + 1) * 20 + px) = v;
    }
    __syncthreads();

    int wid = tid >> 5, lane = tid & 31;
    int row = lane >> 1, xb = (lane & 1) * 8;

    u64 acc[4][4];
#pragma unroll
    for (int a = 0; a < 4; a++)
#pragma unroll
        for (int j = 0; j < 4; j++) acc[a][j] = 0ULL;

    const u64* wb = g_wdup + (size_t)(e * CH + wid * 4) * CH * 12;
    const float* pE = sX + row * 18 + xb;
    const float* pO = sXo + row * 20 + xb;

#pragma unroll 1
    for (int ci = 0; ci < CH; ci++) {
#pragma unroll
        for (int ky = 0; ky < 3; ky++) {
            u64 ev[5], od[4];
            const float* rp = pE + ci * 324 + ky * 18;
            const float* ro = pO + ci * 360 + ky * 20;
#pragma unroll
            for (int j = 0; j < 5; j++) ev[j] = *(const u64*)(rp + 2 * j);
#pragma unroll
            for (int j = 0; j < 4; j++) od[j] = *(const u64*)(ro + 2 * j);
#pragma unroll
            for (int c4 = 0; c4 < 4; c4++) {
                const u64* wp = wb + (c4 * CH + ci) * 12 + ky * 4;
                u64 w0 = wp[0], w1 = wp[1], w2 = wp[2];
#pragma unroll
                for (int j = 0; j < 4; j++) {
                    acc[c4][j] = ffma2(w0, ev[j], acc[c4][j]);
                    acc[c4][j] = ffma2(w1, od[j], acc[c4][j]);
                    acc[c4][j] = ffma2(w2, ev[j + 1], acc[c4][j]);
                }
            }
        }
    }

    // epilogue: y = silu(acc + b); v = t + gamma*wn*y; per-channel sum/sumsq
#pragma unroll
    for (int c4 = 0; c4 < 4; c4++) {
        int co = wid * 4 + c4;
        float bco = EB[e * CH + co];
        float gm = gamma[co] * wn;
        float s = 0.f, ss = 0.f;
#pragma unroll
        for (int j = 0; j < 4; j++) {
            float y0, y1; unpack2(acc[c4][j], y0, y1);
            float a0 = y0 + bco; a0 = a0 / (1.f + __expf(-a0));
            float a1 = y1 + bco; a1 = a1 / (1.f + __expf(-a1));
            float t0 = sX[co * 324 + (row + 1) * 18 + (xb + 1 + 2 * j)];
            float t1 = sX[co * 324 + (row + 1) * 18 + (xb + 2 + 2 * j)];
            float v0 = t0 + gm * a0;
            float v1 = t1 + gm * a1;
            s += v0; ss = fmaf(v0, v0, ss);
            s += v1; ss = fmaf(v1, v1, ss);
        }
#pragma unroll
        for (int off = 16; off > 0; off >>= 1) {
            s  += __shfl_down_sync(0xffffffffu, s, off);
            ss += __shfl_down_sync(0xffffffffu, ss, off);
        }
        if (lane == 0) { g_psum[n * CH + co] = s; g_psumsq[n * CH + co] = ss; }
    }
}

// ============================================================
// K5: GroupNorm(from moments) + pool + LayerNorm + head
// ============================================================
__global__ void __launch_bounds__(256)
k5_head(const float* __restrict__ gnw, const float* __restrict__ gnb,
        const float* __restrict__ lnw, const float* __restrict__ lnb,
        const float* __restrict__ hw, const float* __restrict__ hb,
        float* __restrict__ d_out) {
    __shared__ float sS8[8 * 32], sSS8[8 * 32];
    __shared__ float sS[32], sF[32], sFN[32];
    __shared__ float sMg[8], sRg[8];
    int b = blockIdx.x, tid = threadIdx.x;
    {
        int c = tid & 31, sl = tid >> 5;
        float S = 0.f, SS = 0.f;
        for (int t = sl; t < 196; t += 8) {
            int idx = (b * 196 + t) * CH + c;
            S += g_psum[idx]; SS += g_psumsq[idx];
        }
        sS8[sl * 32 + c] = S; sSS8[sl * 32 + c] = SS;
    }
    __syncthreads();
    if (tid < 32) {
        float S = 0.f, SS = 0.f;
#pragma unroll
        for (int sl = 0; sl < 8; sl++) { S += sS8[sl * 32 + tid]; SS += sSS8[sl * 32 + tid]; }
        sS[tid] = S; sS8[tid] = S; sSS8[tid] = SS;
    }
    __syncthreads();
    if (tid < 8) {
        float S  = sS8[tid * 4] + sS8[tid * 4 + 1] + sS8[tid * 4 + 2] + sS8[tid * 4 + 3];
        float SS = sSS8[tid * 4] + sSS8[tid * 4 + 1] + sSS8[tid * 4 + 2] + sSS8[tid * 4 + 3];
        const float inv = 1.f / (4.f * 50176.f);
        float m = S * inv;
        float ex2 = SS * inv;
        sMg[tid] = m;
        sRg[tid] = rsqrtf(ex2 - m * m + EPSV);
    }
    __syncthreads();
    if (tid < 32) {
        float mx = sS[tid] * (1.f / 50176.f);
        int g = tid >> 2;
        sF[tid] = (mx - sMg[g]) * sRg[g] * gnw[tid] + gnb[tid];
    }
    __syncthreads();
    if (tid == 0) {
        float mu = 0.f;
        for (int c = 0; c < 32; c++) mu += sF[c];
        mu *= (1.f / 32.f);
        float va = 0.f;
        for (int c = 0; c < 32; c++) { float d = sF[c] - mu; va = fmaf(d, d, va); }
        va *= (1.f / 32.f);
        float r = rsqrtf(va + EPSV);
        for (int c = 0; c < 32; c++) sFN[c] = (sF[c] - mu) * r * lnw[c] + lnb[c];
    }
    __syncthreads();
    for (int j = tid; j < NCLS; j += blockDim.x) {
        float a = hb[j];
#pragma unroll
        for (int c = 0; c < 32; c++) a = fmaf(sFN[c], hw[c * NCLS + j], a);
        d_out[b * NCLS + j] = a;
    }
}

// ============================================================
extern "C" void kernel_launch(void* const* d_in, const int* in_sizes, int n_in,
                              void* d_out, int out_size) {
    const float* X        = (const float*)d_in[0];
    const float* stem_w   = (const float*)d_in[1];
    const float* bn_w     = (const float*)d_in[2];
    const float* bn_b     = (const float*)d_in[3];
    const float* gate_w   = (const float*)d_in[4];
    const float* gate_b   = (const float*)d_in[5];
    const float* expert_w = (const float*)d_in[6];
    const float* expert_b = (const float*)d_in[7];
    const float* gamma    = (const float*)d_in[8];
    const float* gn_w     = (const float*)d_in[9];
    const float* gn_b     = (const float*)d_in[10];
    const float* ln_w     = (const float*)d_in[11];
    const float* ln_b     = (const float*)d_in[12];
    const float* head_w   = (const float*)d_in[13];
    const float* head_b   = (const float*)d_in[14];
    float* out = (float*)d_out;

    cudaFuncSetAttribute(k4_expert, cudaFuncAttributeMaxDynamicSharedMemorySize, SMEM_K4);

    k0_wdup<<<(NEXP * CH * CH * 12 + 1023) / 1024, 1024>>>(expert_w);
    k1_stem<<<NTOK, 256>>>(X, stem_w, bn_w, bn_b);
    k2_gate<<<(NTOK + 127) / 128, 128>>>(gate_w, gate_b);
    k3_dispatch<<<1, 512>>>(out);
    k4_expert<<<NTOK, 256, SMEM_K4>>>(expert_b, gamma);
    k5_head<<<8, 256>>>(gn_w, gn_b, ln_w, ln_b, head_w, head_b, out);
}

// round 6
// speedup vs baseline: 1.3792x; 1.3792x over previous
#include <cuda_runtime.h>
#include <math.h>

#define NTOK 1568
#define CH 32
#define NPIX 256
#define NEXP 8
#define CAPN 245
#define NCLS 1000
#define HWD 224
#define HP 14
#define EPSV 1e-5f
#define PI_F 3.14159265358979323846f

typedef unsigned long long u64;

// ---- scratch (no allocations allowed) ----
__device__ float g_tokens[NTOK * CH * NPIX];   // token layout (n,c,py,px)
__device__ float g_cmean[NTOK * CH];
__device__ int   g_top1[NTOK];
__device__ float g_wn[NTOK];
__device__ float g_psum[NTOK * CH];
__device__ float g_psumsq[NTOK * CH];

// ---- f32x2 helpers (Blackwell packed fp32; ptxas never auto-fuses) ----
__device__ __forceinline__ u64 pack2(float x, float y) {
    u64 r; asm("mov.b64 %0, {%1, %2};" : "=l"(r) : "f"(x), "f"(y)); return r;
}
__device__ __forceinline__ void unpack2(u64 v, float& x, float& y) {
    asm("mov.b64 {%0, %1}, %2;" : "=f"(x), "=f"(y) : "l"(v));
}
__device__ __forceinline__ u64 ffma2(u64 a, u64 b, u64 c) {
    u64 d; asm("fma.rn.f32x2 %0, %1, %2, %3;" : "=l"(d) : "l"(a), "l"(b), "l"(c));
    return d;
}
// returns {hi(a), lo(b)}
__device__ __forceinline__ u64 shiftp(u64 a, u64 b) {
    u64 r;
    asm("{\n\t.reg .f32 al, ah, bl, bh;\n\t"
        "mov.b64 {al, ah}, %1;\n\t"
        "mov.b64 {bl, bh}, %2;\n\t"
        "mov.b64 %0, {ah, bl};\n\t}"
        : "=l"(r) : "l"(a), "l"(b));
    return r;
}

// ============================================================
// K1: stem conv3x3 (3->32) + BN + SiLU -> tokens; fused channel means
// ============================================================
__global__ void __launch_bounds__(256)
k1_stem(const float* __restrict__ X, const float* __restrict__ W,
        const float* __restrict__ bnw, const float* __restrict__ bnb) {
    __shared__ __align__(16) float sIn[3 * 18 * 18];
    __shared__ __align__(16) float sW[32 * 28];   // padded to 28/row for b64 pairs
    __shared__ float sBw[32], sBb[32];
    __shared__ float sPart[8 * 32];
    int n = blockIdx.x;
    int b = n / 196, pr = (n % 196) / HP, pc = n % HP;
    int tid = threadIdx.x;

    for (int i = tid; i < 3 * 18 * 18; i += 256) {
        int ci = i / 324, r = (i % 324) / 18, c = i % 18;
        int gy = pr * 16 + r - 1, gx = pc * 16 + c - 1;
        float v = 0.f;
        if (gy >= 0 && gy < HWD && gx >= 0 && gx < HWD)
            v = X[((b * 3 + ci) * HWD + gy) * HWD + gx];
        sIn[i] = v;
    }
    for (int i = tid; i < 32 * 28; i += 256) {
        int co = i / 28, k = i % 28;
        sW[i] = (k < 27) ? W[co * 27 + k] : 0.f;
    }
    if (tid < 32) { sBw[tid] = bnw[tid]; sBb[tid] = bnb[tid]; }
    __syncthreads();

    int py = tid >> 4, px = tid & 15;
    float xin[28];
#pragma unroll
    for (int ci = 0; ci < 3; ci++)
#pragma unroll
        for (int dy = 0; dy < 3; dy++)
#pragma unroll
            for (int dx = 0; dx < 3; dx++)
                xin[ci * 9 + dy * 3 + dx] = sIn[ci * 324 + (py + dy) * 18 + (px + dx)];
    xin[27] = 0.f;
    u64 xp[14];
#pragma unroll
    for (int j = 0; j < 14; j++) xp[j] = pack2(xin[2 * j], xin[2 * j + 1]);

    int lane = tid & 31, wid = tid >> 5;
    for (int co = 0; co < 32; co++) {
        u64 acc = 0ULL;
#pragma unroll
        for (int j = 0; j < 14; j++)
            acc = ffma2(*(const u64*)(sW + co * 28 + 2 * j), xp[j], acc);
        float a0, a1; unpack2(acc, a0, a1);
        float a = a0 + a1;
        a = a * sBw[co] + sBb[co];
        float s = a / (1.f + __expf(-a));
        g_tokens[(n * CH + co) * NPIX + tid] = s;
        float ws = s;
#pragma unroll
        for (int off = 16; off > 0; off >>= 1)
            ws += __shfl_down_sync(0xffffffffu, ws, off);
        if (lane == 0) sPart[wid * 32 + co] = ws;
    }
    __syncthreads();
    if (tid < 32) {
        float sum = 0.f;
#pragma unroll
        for (int w = 0; w < 8; w++) sum += sPart[w * 32 + tid];
        g_cmean[n * CH + tid] = sum * (1.f / 256.f);
    }
}

// ============================================================
// K3: gate + softmax + capacity scan + losses. One block, 512 threads.
// ============================================================
__global__ void __launch_bounds__(512)
k3_gate_dispatch(const float* __restrict__ gate_w,
                 const float* __restrict__ gate_b,
                 float* __restrict__ d_out) {
    __shared__ float sGw[50 * 8];
    __shared__ float sGb[8];
    __shared__ float tab[14][9];
    __shared__ int   sT[NTOK];
    __shared__ float sPtop[NTOK];
    __shared__ float sWred[16][17];
    __shared__ int   sWC[16 * 9];
    __shared__ int   sRun[8];
    int tid = threadIdx.x;
    int lane = tid & 31, wid = tid >> 5;

    for (int i = tid; i < 400; i += 512) sGw[i] = gate_w[i];
    if (tid < 8) { sGb[tid] = gate_b[tid]; sRun[tid] = 0; }
    if (tid < 144) sWC[tid] = 0;
    if (tid < 56) {
        int b2 = tid >> 2, k = tid & 3;
        float f = (float)(1 << k) * PI_F;
        float ss = 0.f, cs = 0.f;
        for (int r = 0; r < 16; r++) {
            float ang = f * ((16.f * b2 + (float)r + 0.5f) / 224.f);
            ss += sinf(ang); cs += cosf(ang);
        }
        tab[b2][1 + 2 * k] = ss * (1.f / 16.f);
        tab[b2][2 + 2 * k] = cs * (1.f / 16.f);
    } else if (tid < 70) {
        int b2 = tid - 56;
        tab[b2][0] = (16.f * b2 + 8.f) / 224.f;
    }
    __syncthreads();

    float part[17];
#pragma unroll
    for (int q = 0; q < 17; q++) part[q] = 0.f;

    for (int n = tid; n < NTOK; n += 512) {
        int pr = (n % 196) / HP, pc = n % HP;
        float l[8];
#pragma unroll
        for (int e = 0; e < 8; e++) l[e] = sGb[e];
        const float4* cm4 = (const float4*)&g_cmean[n * CH];
#pragma unroll
        for (int i4 = 0; i4 < 8; i4++) {
            float4 v4 = cm4[i4];
            float vv[4] = {v4.x, v4.y, v4.z, v4.w};
#pragma unroll
            for (int q = 0; q < 4; q++) {
                int i = i4 * 4 + q;
#pragma unroll
                for (int e = 0; e < 8; e++) l[e] = fmaf(vv[q], sGw[i * 8 + e], l[e]);
            }
        }
        {
            float v0 = tab[pr][0], v1 = tab[pc][0];
#pragma unroll
            for (int e = 0; e < 8; e++) {
                l[e] = fmaf(v0, sGw[32 * 8 + e], l[e]);
                l[e] = fmaf(v1, sGw[33 * 8 + e], l[e]);
            }
        }
#pragma unroll
        for (int k = 0; k < 4; k++) {
#pragma unroll
            for (int sub = 0; sub < 4; sub++) {
                float v = (sub < 2) ? tab[pr][1 + 2 * k + sub] : tab[pc][1 + 2 * k + (sub - 2)];
#pragma unroll
                for (int e = 0; e < 8; e++)
                    l[e] = fmaf(v, sGw[(34 + 4 * k + sub) * 8 + e], l[e]);
            }
        }
        float mx = l[0]; int am = 0;
#pragma unroll
        for (int e = 1; e < 8; e++) if (l[e] > mx) { mx = l[e]; am = e; }
        float pe[8], se = 0.f;
#pragma unroll
        for (int e = 0; e < 8; e++) { pe[e] = __expf(l[e] - mx); se += pe[e]; }
        float inv = 1.f / se;
#pragma unroll
        for (int e = 0; e < 8; e++) part[1 + e] += pe[e] * inv;
        float lse = mx + __logf(se);
        part[0] += lse * lse;
        part[9 + am] += 1.f;
        sT[n] = am;
        g_top1[n] = am;
        sPtop[n] = pe[am] * inv;
    }
    __syncthreads();

    // capacity scan: chunked ballot prefix, exact token-index order
    for (int c = 0; c < 4; c++) {
        int n = c * 512 + tid;
        bool act = n < NTOK;
        int e = act ? sT[n] : 8;
        unsigned m = __match_any_sync(0xffffffffu, e);
        int lr = __popc(m & ((1u << lane) - 1u));
        if (lr == 0) sWC[wid * 9 + e] = __popc(m);
        __syncthreads();
        if (act) {
            int base = sRun[e];
            for (int w2 = 0; w2 < wid; w2++) base += sWC[w2 * 9 + e];
            int rank = base + lr;
            g_wn[n] = (rank < CAPN) ? sPtop[n] : 0.f;
        }
        int s = 0;
        if (tid < 8) for (int w2 = 0; w2 < 16; w2++) s += sWC[w2 * 9 + tid];
        __syncthreads();
        if (tid < 8) sRun[tid] += s;
        if (tid < 144) sWC[tid] = 0;
        __syncthreads();
    }

    // loss reductions: warp shuffle + one cross-warp pass
#pragma unroll
    for (int q = 0; q < 17; q++) {
#pragma unroll
        for (int off = 16; off > 0; off >>= 1)
            part[q] += __shfl_down_sync(0xffffffffu, part[q], off);
        if (lane == 0) sWred[wid][q] = part[q];
    }
    __syncthreads();
    if (tid == 0) {
        float res[17];
#pragma unroll
        for (int q = 0; q < 17; q++) {
            float s = 0.f;
            for (int w2 = 0; w2 < 16; w2++) s += sWred[w2][q];
            res[q] = s;
        }
        float z = res[0] / (float)NTOK;
        float imb = 0.f;
        for (int e = 0; e < 8; e++) imb += res[1 + e] * res[9 + e];
        imb *= (float)NEXP / ((float)NTOK * (float)NTOK);
        d_out[8000] = z;
        d_out[8001] = imb;
    }
}

// ============================================================
// K4: expert conv3x3 (32->32) + SiLU + combine.
// Weights staged once per block in smem (36 KB); image in stride-20
// smem for aligned LDS.128 row loads; f32x2 mainloop.
// ============================================================
#define SXSTR 20
#define SX_FLOATS (CH * 18 * SXSTR)      // 11520 floats (46 KB)
#define SW_FLOATS (CH * CH * 9)          // 9216 floats (36 KB)
#define SMEM_K4 ((SX_FLOATS + SW_FLOATS) * 4)

__global__ void __launch_bounds__(256, 2)
k4_expert(const float* __restrict__ EW, const float* __restrict__ EB,
          const float* __restrict__ gamma) {
    extern __shared__ __align__(16) float smem[];
    float* sX = smem;                    // [c][18][20]; pixel (r,x) at [r+1][x+1]
    float* sW = smem + SX_FLOATS;        // [co][ci][9]
    int n = blockIdx.x;
    int tid = threadIdx.x;
    float wn = g_wn[n];
    int e = g_top1[n];
    bool active = (wn != 0.f);

    {
        u64* z = (u64*)sX;
        for (int i = tid; i < SX_FLOATS / 2; i += 256) z[i] = 0ULL;
    }
    __syncthreads();
    const float4* src = (const float4*)(g_tokens + (size_t)n * CH * NPIX);
    for (int i = tid; i < CH * NPIX / 4; i += 256) {
        float4 v = src[i];
        int c = i >> 6;
        int p = (i & 63) * 4;
        float* d = sX + c * 360 + ((p >> 4) + 1) * SXSTR + (p & 15) + 1;
        d[0] = v.x; d[1] = v.y; d[2] = v.z; d[3] = v.w;
    }
    if (active) {
        const float4* wsrc = (const float4*)(EW + (size_t)e * SW_FLOATS);
        float4* wdst = (float4*)sW;
        for (int i = tid; i < SW_FLOATS / 4; i += 256) wdst[i] = wsrc[i];
    }
    __syncthreads();

    int wid = tid >> 5, lane = tid & 31;
    int row = lane >> 1, xb = (lane & 1) * 8;

    if (!active) {
        // dropped token: output = input; emit moments of t directly
#pragma unroll
        for (int c4 = 0; c4 < 4; c4++) {
            int co = wid * 4 + c4;
            const float* tp = sX + co * 360 + (row + 1) * SXSTR + xb + 1;
            float s = 0.f, ss = 0.f;
#pragma unroll
            for (int p = 0; p < 8; p++) { float v = tp[p]; s += v; ss = fmaf(v, v, ss); }
#pragma unroll
            for (int off = 16; off > 0; off >>= 1) {
                s  += __shfl_down_sync(0xffffffffu, s, off);
                ss += __shfl_down_sync(0xffffffffu, ss, off);
            }
            if (lane == 0) { g_psum[n * CH + co] = s; g_psumsq[n * CH + co] = ss; }
        }
        return;
    }

    u64 acc[4][4];
#pragma unroll
    for (int a = 0; a < 4; a++)
#pragma unroll
        for (int j = 0; j < 4; j++) acc[a][j] = 0ULL;

    const float* pX = sX + row * SXSTR + xb;
    const float* wbase = sW + (wid * 4) * CH * 9;

#pragma unroll 1
    for (int ci = 0; ci < CH; ci++) {
        const float* rb = pX + ci * 360;
        u64 ev[3][5];
#pragma unroll
        for (int r = 0; r < 3; r++) {
            const float* rp = rb + r * SXSTR;
            ulonglong2 A = *(const ulonglong2*)rp;        // x0..x3
            ulonglong2 B = *(const ulonglong2*)(rp + 4);  // x4..x7
            u64 C = *(const u64*)(rp + 8);                // x8,x9
            ev[r][0] = A.x; ev[r][1] = A.y; ev[r][2] = B.x; ev[r][3] = B.y; ev[r][4] = C;
        }
        u64 od[3][4];
#pragma unroll
        for (int r = 0; r < 3; r++)
#pragma unroll
            for (int j = 0; j < 4; j++) od[r][j] = shiftp(ev[r][j], ev[r][j + 1]);
#pragma unroll
        for (int c4 = 0; c4 < 4; c4++) {
            const float* wp = wbase + (c4 * CH + ci) * 9;
#pragma unroll
            for (int ky = 0; ky < 3; ky++) {
                float f0 = wp[ky * 3 + 0], f1 = wp[ky * 3 + 1], f2 = wp[ky * 3 + 2];
                u64 w0 = pack2(f0, f0);
                u64 w1 = pack2(f1, f1);
                u64 w2 = pack2(f2, f2);
#pragma unroll
                for (int j = 0; j < 4; j++) {
                    acc[c4][j] = ffma2(w0, ev[ky][j], acc[c4][j]);
                    acc[c4][j] = ffma2(w1, od[ky][j], acc[c4][j]);
                    acc[c4][j] = ffma2(w2, ev[ky][j + 1], acc[c4][j]);
                }
            }
        }
    }

    // epilogue: y = silu(acc + b); v = t + gamma*wn*y; per-channel sum/sumsq
#pragma unroll
    for (int c4 = 0; c4 < 4; c4++) {
        int co = wid * 4 + c4;
        float bco = EB[e * CH + co];
        float gm = gamma[co] * wn;
        float s = 0.f, ss = 0.f;
        const float* tp = sX + co * 360 + (row + 1) * SXSTR + xb + 1;
#pragma unroll
        for (int j = 0; j < 4; j++) {
            float y0, y1; unpack2(acc[c4][j], y0, y1);
            float a0 = y0 + bco; a0 = a0 / (1.f + __expf(-a0));
            float a1 = y1 + bco; a1 = a1 / (1.f + __expf(-a1));
            float v0 = tp[2 * j]     + gm * a0;
            float v1 = tp[2 * j + 1] + gm * a1;
            s += v0; ss = fmaf(v0, v0, ss);
            s += v1; ss = fmaf(v1, v1, ss);
        }
#pragma unroll
        for (int off = 16; off > 0; off >>= 1) {
            s  += __shfl_down_sync(0xffffffffu, s, off);
            ss += __shfl_down_sync(0xffffffffu, ss, off);
        }
        if (lane == 0) { g_psum[n * CH + co] = s; g_psumsq[n * CH + co] = ss; }
    }
}

// ============================================================
// K5: GroupNorm(from moments) + pool + LayerNorm + head
// ============================================================
__global__ void __launch_bounds__(256)
k5_head(const float* __restrict__ gnw, const float* __restrict__ gnb,
        const float* __restrict__ lnw, const float* __restrict__ lnb,
        const float* __restrict__ hw, const float* __restrict__ hb,
        float* __restrict__ d_out) {
    __shared__ float sS8[8 * 32], sSS8[8 * 32];
    __shared__ float sS[32], sF[32], sFN[32];
    __shared__ float sMg[8], sRg[8];
    int b = blockIdx.x, tid = threadIdx.x;
    {
        int c = tid & 31, sl = tid >> 5;
        float S = 0.f, SS = 0.f;
        for (int t = sl; t < 196; t += 8) {
            int idx = (b * 196 + t) * CH + c;
            S += g_psum[idx]; SS += g_psumsq[idx];
        }
        sS8[sl * 32 + c] = S; sSS8[sl * 32 + c] = SS;
    }
    __syncthreads();
    if (tid < 32) {
        float S = 0.f, SS = 0.f;
#pragma unroll
        for (int sl = 0; sl < 8; sl++) { S += sS8[sl * 32 + tid]; SS += sSS8[sl * 32 + tid]; }
        sS[tid] = S; sS8[tid] = S; sSS8[tid] = SS;
    }
    __syncthreads();
    if (tid < 8) {
        float S  = sS8[tid * 4] + sS8[tid * 4 + 1] + sS8[tid * 4 + 2] + sS8[tid * 4 + 3];
        float SS = sSS8[tid * 4] + sSS8[tid * 4 + 1] + sSS8[tid * 4 + 2] + sSS8[tid * 4 + 3];
        const float inv = 1.f / (4.f * 50176.f);
        float m = S * inv;
        float ex2 = SS * inv;
        sMg[tid] = m;
        sRg[tid] = rsqrtf(ex2 - m * m + EPSV);
    }
    __syncthreads();
    if (tid < 32) {
        float mx = sS[tid] * (1.f / 50176.f);
        int g = tid >> 2;
        sF[tid] = (mx - sMg[g]) * sRg[g] * gnw[tid] + gnb[tid];
    }
    __syncthreads();
    if (tid == 0) {
        float mu = 0.f;
        for (int c = 0; c < 32; c++) mu += sF[c];
        mu *= (1.f / 32.f);
        float va = 0.f;
        for (int c = 0; c < 32; c++) { float d = sF[c] - mu; va = fmaf(d, d, va); }
        va *= (1.f / 32.f);
        float r = rsqrtf(va + EPSV);
        for (int c = 0; c < 32; c++) sFN[c] = (sF[c] - mu) * r * lnw[c] + lnb[c];
    }
    __syncthreads();
    for (int j = tid; j < NCLS; j += blockDim.x) {
        float a = hb[j];
#pragma unroll
        for (int c = 0; c < 32; c++) a = fmaf(sFN[c], hw[c * NCLS + j], a);
        d_out[b * NCLS + j] = a;
    }
}

// ============================================================
extern "C" void kernel_launch(void* const* d_in, const int* in_sizes, int n_in,
                              void* d_out, int out_size) {
    const float* X        = (const float*)d_in[0];
    const float* stem_w   = (const float*)d_in[1];
    const float* bn_w     = (const float*)d_in[2];
    const float* bn_b     = (const float*)d_in[3];
    const float* gate_w   = (const float*)d_in[4];
    const float* gate_b   = (const float*)d_in[5];
    const float* expert_w = (const float*)d_in[6];
    const float* expert_b = (const float*)d_in[7];
    const float* gamma    = (const float*)d_in[8];
    const float* gn_w     = (const float*)d_in[9];
    const float* gn_b     = (const float*)d_in[10];
    const float* ln_w     = (const float*)d_in[11];
    const float* ln_b     = (const float*)d_in[12];
    const float* head_w   = (const float*)d_in[13];
    const float* head_b   = (const float*)d_in[14];
    float* out = (float*)d_out;

    cudaFuncSetAttribute(k4_expert, cudaFuncAttributeMaxDynamicSharedMemorySize, SMEM_K4);

    k1_stem<<<NTOK, 256>>>(X, stem_w, bn_w, bn_b);
    k3_gate_dispatch<<<1, 512>>>(gate_w, gate_b, out);
    k4_expert<<<NTOK, 256, SMEM_K4>>>(expert_w, expert_b, gamma);
    k5_head<<<8, 256>>>(gn_w, gn_b, ln_w, ln_b, head_w, head_b, out);
}

// round 7
// speedup vs baseline: 1.6493x; 1.1958x over previous
#include <cuda_runtime.h>
#include <math.h>

#define NTOK 1568
#define CH 32
#define NPIX 256
#define NEXP 8
#define CAPN 245
#define NCLS 1000
#define HWD 224
#define HP 14
#define EPSV 1e-5f
#define PI_F 3.14159265358979323846f

typedef unsigned long long u64;

// ---- scratch (no allocations allowed) ----
__device__ float g_tokens[NTOK * CH * NPIX];   // token layout (n,c,py,px)
__device__ float g_cmean[NTOK * CH];
__device__ int   g_top1[NTOK];
__device__ float g_ptop[NTOK];
__device__ float g_lse[NTOK];
__device__ float g_probs[NTOK * NEXP];
__device__ float g_wn[NTOK];
__device__ float g_psum[NTOK * CH];
__device__ float g_psumsq[NTOK * CH];

// ---- f32x2 helpers (Blackwell packed fp32; ptxas never auto-fuses) ----
__device__ __forceinline__ u64 pack2(float x, float y) {
    u64 r; asm("mov.b64 %0, {%1, %2};" : "=l"(r) : "f"(x), "f"(y)); return r;
}
__device__ __forceinline__ void unpack2(u64 v, float& x, float& y) {
    asm("mov.b64 {%0, %1}, %2;" : "=f"(x), "=f"(y) : "l"(v));
}
__device__ __forceinline__ u64 ffma2(u64 a, u64 b, u64 c) {
    u64 d; asm("fma.rn.f32x2 %0, %1, %2, %3;" : "=l"(d) : "l"(a), "l"(b), "l"(c));
    return d;
}
// returns {hi(a), lo(b)}
__device__ __forceinline__ u64 shiftp(u64 a, u64 b) {
    u64 r;
    asm("{\n\t.reg .f32 al, ah, bl, bh;\n\t"
        "mov.b64 {al, ah}, %1;\n\t"
        "mov.b64 {bl, bh}, %2;\n\t"
        "mov.b64 %0, {ah, bl};\n\t}"
        : "=l"(r) : "l"(a), "l"(b));
    return r;
}

// ============================================================
// K1: stem conv3x3 (3->32) + BN + SiLU -> tokens; fused channel means
// ============================================================
__global__ void __launch_bounds__(256)
k1_stem(const float* __restrict__ X, const float* __restrict__ W,
        const float* __restrict__ bnw, const float* __restrict__ bnb) {
    __shared__ __align__(16) float sIn[3 * 18 * 18];
    __shared__ __align__(16) float sW[32 * 28];   // padded to 28/row for b64 pairs
    __shared__ float sBw[32], sBb[32];
    __shared__ float sPart[8 * 32];
    int n = blockIdx.x;
    int b = n / 196, pr = (n % 196) / HP, pc = n % HP;
    int tid = threadIdx.x;

    for (int i = tid; i < 3 * 18 * 18; i += 256) {
        int ci = i / 324, r = (i % 324) / 18, c = i % 18;
        int gy = pr * 16 + r - 1, gx = pc * 16 + c - 1;
        float v = 0.f;
        if (gy >= 0 && gy < HWD && gx >= 0 && gx < HWD)
            v = X[((b * 3 + ci) * HWD + gy) * HWD + gx];
        sIn[i] = v;
    }
    for (int i = tid; i < 32 * 28; i += 256) {
        int co = i / 28, k = i % 28;
        sW[i] = (k < 27) ? W[co * 27 + k] : 0.f;
    }
    if (tid < 32) { sBw[tid] = bnw[tid]; sBb[tid] = bnb[tid]; }
    __syncthreads();

    int py = tid >> 4, px = tid & 15;
    float xin[28];
#pragma unroll
    for (int ci = 0; ci < 3; ci++)
#pragma unroll
        for (int dy = 0; dy < 3; dy++)
#pragma unroll
            for (int dx = 0; dx < 3; dx++)
                xin[ci * 9 + dy * 3 + dx] = sIn[ci * 324 + (py + dy) * 18 + (px + dx)];
    xin[27] = 0.f;
    u64 xp[14];
#pragma unroll
    for (int j = 0; j < 14; j++) xp[j] = pack2(xin[2 * j], xin[2 * j + 1]);

    int lane = tid & 31, wid = tid >> 5;
    for (int co = 0; co < 32; co++) {
        u64 acc = 0ULL;
#pragma unroll
        for (int j = 0; j < 14; j++)
            acc = ffma2(*(const u64*)(sW + co * 28 + 2 * j), xp[j], acc);
        float a0, a1; unpack2(acc, a0, a1);
        float a = a0 + a1;
        a = a * sBw[co] + sBb[co];
        float s = a / (1.f + __expf(-a));
        g_tokens[(n * CH + co) * NPIX + tid] = s;
        float ws = s;
#pragma unroll
        for (int off = 16; off > 0; off >>= 1)
            ws += __shfl_down_sync(0xffffffffu, ws, off);
        if (lane == 0) sPart[wid * 32 + co] = ws;
    }
    __syncthreads();
    if (tid < 32) {
        float sum = 0.f;
#pragma unroll
        for (int w = 0; w < 8; w++) sum += sPart[w * 32 + tid];
        g_cmean[n * CH + tid] = sum * (1.f / 256.f);
    }
}

// ============================================================
// K2: gate — one thread per token. 13 blocks x 128 threads.
// ============================================================
__global__ void __launch_bounds__(128)
k2_gate(const float* __restrict__ gate_w, const float* __restrict__ gate_b) {
    __shared__ float sGw[50 * 8];
    __shared__ float sGb[8];
    __shared__ float tab[14][9];
    int tid = threadIdx.x;

    for (int i = tid; i < 400; i += 128) sGw[i] = gate_w[i];
    if (tid < 8) sGb[tid] = gate_b[tid];
    if (tid < 56) {
        int b2 = tid >> 2, k = tid & 3;
        float f = (float)(1 << k) * PI_F;
        float ss = 0.f, cs = 0.f;
        for (int r = 0; r < 16; r++) {
            float ang = f * ((16.f * b2 + (float)r + 0.5f) / 224.f);
            ss += sinf(ang); cs += cosf(ang);
        }
        tab[b2][1 + 2 * k] = ss * (1.f / 16.f);
        tab[b2][2 + 2 * k] = cs * (1.f / 16.f);
    } else if (tid < 70) {
        int b2 = tid - 56;
        tab[b2][0] = (16.f * b2 + 8.f) / 224.f;
    }
    __syncthreads();

    int n = blockIdx.x * 128 + tid;
    if (n >= NTOK) return;
    int pr = (n % 196) / HP, pc = n % HP;

    float l[8];
#pragma unroll
    for (int e = 0; e < 8; e++) l[e] = sGb[e];
    const float4* cm4 = (const float4*)&g_cmean[n * CH];
#pragma unroll
    for (int i4 = 0; i4 < 8; i4++) {
        float4 v4 = cm4[i4];
        float vv[4] = {v4.x, v4.y, v4.z, v4.w};
#pragma unroll
        for (int q = 0; q < 4; q++) {
            int i = i4 * 4 + q;
#pragma unroll
            for (int e = 0; e < 8; e++) l[e] = fmaf(vv[q], sGw[i * 8 + e], l[e]);
        }
    }
    {
        float v0 = tab[pr][0], v1 = tab[pc][0];
#pragma unroll
        for (int e = 0; e < 8; e++) {
            l[e] = fmaf(v0, sGw[32 * 8 + e], l[e]);
            l[e] = fmaf(v1, sGw[33 * 8 + e], l[e]);
        }
    }
#pragma unroll
    for (int k = 0; k < 4; k++) {
#pragma unroll
        for (int sub = 0; sub < 4; sub++) {
            float v = (sub < 2) ? tab[pr][1 + 2 * k + sub] : tab[pc][1 + 2 * k + (sub - 2)];
#pragma unroll
            for (int e = 0; e < 8; e++)
                l[e] = fmaf(v, sGw[(34 + 4 * k + sub) * 8 + e], l[e]);
        }
    }
    float mx = l[0]; int am = 0;
#pragma unroll
    for (int e = 1; e < 8; e++) if (l[e] > mx) { mx = l[e]; am = e; }
    float pe[8], se = 0.f;
#pragma unroll
    for (int e = 0; e < 8; e++) { pe[e] = __expf(l[e] - mx); se += pe[e]; }
    float inv = 1.f / se;
#pragma unroll
    for (int e = 0; e < 8; e++) g_probs[n * 8 + e] = pe[e] * inv;
    g_top1[n] = am;
    g_ptop[n] = pe[am] * inv;
    g_lse[n] = mx + __logf(se);
}

// ============================================================
// K3: capacity scan (ballot, exact token order) + loss reductions
// ============================================================
__global__ void __launch_bounds__(512)
k3_dispatch(float* __restrict__ d_out) {
    __shared__ int   sT[NTOK];
    __shared__ float sWred[16][17];
    __shared__ int   sWC[16 * 9];
    __shared__ int   sRun[8];
    int tid = threadIdx.x;
    int lane = tid & 31, wid = tid >> 5;

    for (int i = tid; i < NTOK; i += 512) sT[i] = g_top1[i];
    if (tid < 8) sRun[tid] = 0;
    if (tid < 144) sWC[tid] = 0;
    __syncthreads();

    float part[17];
#pragma unroll
    for (int q = 0; q < 17; q++) part[q] = 0.f;
    for (int n = tid; n < NTOK; n += 512) {
        float lse = g_lse[n];
        part[0] += lse * lse;
        const float4* p4 = (const float4*)&g_probs[n * 8];
        float4 a = p4[0], b = p4[1];
        part[1] += a.x; part[2] += a.y; part[3] += a.z; part[4] += a.w;
        part[5] += b.x; part[6] += b.y; part[7] += b.z; part[8] += b.w;
        part[9 + sT[n]] += 1.f;
    }

    // capacity scan: chunked ballot prefix, exact token-index order
    for (int c = 0; c < 4; c++) {
        int n = c * 512 + tid;
        bool act = n < NTOK;
        int e = act ? sT[n] : 8;
        unsigned m = __match_any_sync(0xffffffffu, e);
        int lr = __popc(m & ((1u << lane) - 1u));
        if (lr == 0) sWC[wid * 9 + e] = __popc(m);
        __syncthreads();
        if (act) {
            int base = sRun[e];
            for (int w2 = 0; w2 < wid; w2++) base += sWC[w2 * 9 + e];
            int rank = base + lr;
            g_wn[n] = (rank < CAPN) ? g_ptop[n] : 0.f;
        }
        int s = 0;
        if (tid < 8) for (int w2 = 0; w2 < 16; w2++) s += sWC[w2 * 9 + tid];
        __syncthreads();
        if (tid < 8) sRun[tid] += s;
        if (tid < 144) sWC[tid] = 0;
        __syncthreads();
    }

    // loss reductions: warp shuffle + single cross-warp pass
#pragma unroll
    for (int q = 0; q < 17; q++) {
#pragma unroll
        for (int off = 16; off > 0; off >>= 1)
            part[q] += __shfl_down_sync(0xffffffffu, part[q], off);
        if (lane == 0) sWred[wid][q] = part[q];
    }
    __syncthreads();
    if (tid == 0) {
        float res[17];
#pragma unroll
        for (int q = 0; q < 17; q++) {
            float s = 0.f;
            for (int w2 = 0; w2 < 16; w2++) s += sWred[w2][q];
            res[q] = s;
        }
        float z = res[0] / (float)NTOK;
        float imb = 0.f;
        for (int e = 0; e < 8; e++) imb += res[1 + e] * res[9 + e];
        imb *= (float)NEXP / ((float)NTOK * (float)NTOK);
        d_out[8000] = z;
        d_out[8001] = imb;
    }
}

// ============================================================
// K4: expert conv3x3 (32->32) + SiLU + combine.
// f32x2 mainloop, per-ky streaming (low live-register count),
// scalar uniform __ldg weights, occupancy-3 target.
// ============================================================
__global__ void __launch_bounds__(256, 3)
k4_expert(const float* __restrict__ EW, const float* __restrict__ EB,
          const float* __restrict__ gamma) {
    __shared__ __align__(16) float sX[CH * 324];  // [c][18][18]; pixel (r,x) at [r+1][x+1]
    int n = blockIdx.x;
    int tid = threadIdx.x;
    float wn = g_wn[n];
    int e = g_top1[n];
    bool active = (wn != 0.f);

    {
        u64* z = (u64*)sX;
        for (int i = tid; i < CH * 324 / 2; i += 256) z[i] = 0ULL;
    }
    __syncthreads();
    const float4* src = (const float4*)(g_tokens + (size_t)n * CH * NPIX);
    for (int i = tid; i < CH * NPIX / 4; i += 256) {
        float4 v = src[i];
        int c = i >> 6;
        int p = (i & 63) * 4;
        float* d = sX + c * 324 + ((p >> 4) + 1) * 18 + (p & 15) + 1;
        d[0] = v.x; d[1] = v.y; d[2] = v.z; d[3] = v.w;
    }
    __syncthreads();

    int wid = tid >> 5, lane = tid & 31;
    int row = lane >> 1, xb = (lane & 1) * 8;

    if (!active) {
        // dropped token: output = input; emit moments of t directly
#pragma unroll
        for (int c4 = 0; c4 < 4; c4++) {
            int co = wid * 4 + c4;
            const float* tp = sX + co * 324 + (row + 1) * 18 + xb + 1;
            float s = 0.f, ss = 0.f;
#pragma unroll
            for (int p = 0; p < 8; p++) { float v = tp[p]; s += v; ss = fmaf(v, v, ss); }
#pragma unroll
            for (int off = 16; off > 0; off >>= 1) {
                s  += __shfl_down_sync(0xffffffffu, s, off);
                ss += __shfl_down_sync(0xffffffffu, ss, off);
            }
            if (lane == 0) { g_psum[n * CH + co] = s; g_psumsq[n * CH + co] = ss; }
        }
        return;
    }

    u64 acc[4][4];
#pragma unroll
    for (int a = 0; a < 4; a++)
#pragma unroll
        for (int j = 0; j < 4; j++) acc[a][j] = 0ULL;

    const float* wb = EW + ((size_t)e * CH + wid * 4) * CH * 9;
    const float* pX = sX + row * 18 + xb;

#pragma unroll 1
    for (int ci = 0; ci < CH; ci++) {
        const float* rb = pX + ci * 324;
#pragma unroll
        for (int ky = 0; ky < 3; ky++) {
            const float* rp = rb + ky * 18;
            u64 ev[5], od[4];
#pragma unroll
            for (int j = 0; j < 5; j++) ev[j] = *(const u64*)(rp + 2 * j);
#pragma unroll
            for (int j = 0; j < 4; j++) od[j] = shiftp(ev[j], ev[j + 1]);
#pragma unroll
            for (int c4 = 0; c4 < 4; c4++) {
                const float* wp = wb + (c4 * CH + ci) * 9 + ky * 3;
                float f0 = __ldg(wp), f1 = __ldg(wp + 1), f2 = __ldg(wp + 2);
                u64 w0 = pack2(f0, f0);
                u64 w1 = pack2(f1, f1);
                u64 w2 = pack2(f2, f2);
#pragma unroll
                for (int j = 0; j < 4; j++) {
                    acc[c4][j] = ffma2(w0, ev[j], acc[c4][j]);
                    acc[c4][j] = ffma2(w1, od[j], acc[c4][j]);
                    acc[c4][j] = ffma2(w2, ev[j + 1], acc[c4][j]);
                }
            }
        }
    }

    // epilogue: y = silu(acc + b); v = t + gamma*wn*y; per-channel sum/sumsq
#pragma unroll
    for (int c4 = 0; c4 < 4; c4++) {
        int co = wid * 4 + c4;
        float bco = __ldg(EB + e * CH + co);
        float gm = __ldg(gamma + co) * wn;
        float s = 0.f, ss = 0.f;
        const float* tp = sX + co * 324 + (row + 1) * 18 + xb + 1;
#pragma unroll
        for (int j = 0; j < 4; j++) {
            float y0, y1; unpack2(acc[c4][j], y0, y1);
            float a0 = y0 + bco; a0 = a0 / (1.f + __expf(-a0));
            float a1 = y1 + bco; a1 = a1 / (1.f + __expf(-a1));
            float v0 = tp[2 * j]     + gm * a0;
            float v1 = tp[2 * j + 1] + gm * a1;
            s += v0; ss = fmaf(v0, v0, ss);
            s += v1; ss = fmaf(v1, v1, ss);
        }
#pragma unroll
        for (int off = 16; off > 0; off >>= 1) {
            s  += __shfl_down_sync(0xffffffffu, s, off);
            ss += __shfl_down_sync(0xffffffffu, ss, off);
        }
        if (lane == 0) { g_psum[n * CH + co] = s; g_psumsq[n * CH + co] = ss; }
    }
}

// ============================================================
// K5: GroupNorm(from moments) + pool + LayerNorm + head
// 1024 threads: 32 token-slices x 32 channels, then head in one pass
// ============================================================
__global__ void __launch_bounds__(1024)
k5_head(const float* __restrict__ gnw, const float* __restrict__ gnb,
        const float* __restrict__ lnw, const float* __restrict__ lnb,
        const float* __restrict__ hw, const float* __restrict__ hb,
        float* __restrict__ d_out) {
    __shared__ float sS32[32 * 32], sSS32[32 * 32];
    __shared__ float sS[32], sF[32], sFN[32];
    __shared__ float sMg[8], sRg[8];
    int b = blockIdx.x, tid = threadIdx.x;
    {
        int c = tid & 31, sl = tid >> 5;   // 32 slices x 32 channels
        float S = 0.f, SS = 0.f;
        for (int t = sl; t < 196; t += 32) {
            int idx = (b * 196 + t) * CH + c;
            S += g_psum[idx]; SS += g_psumsq[idx];
        }
        sS32[sl * 32 + c] = S; sSS32[sl * 32 + c] = SS;
    }
    __syncthreads();
    if (tid < 32) {
        float S = 0.f, SS = 0.f;
#pragma unroll
        for (int sl = 0; sl < 32; sl++) { S += sS32[sl * 32 + tid]; SS += sSS32[sl * 32 + tid]; }
        sS[tid] = S; sS32[tid] = S; sSS32[tid] = SS;   // row 0 = channel totals
    }
    __syncthreads();
    if (tid < 8) {
        float S  = sS32[tid * 4] + sS32[tid * 4 + 1] + sS32[tid * 4 + 2] + sS32[tid * 4 + 3];
        float SS = sSS32[tid * 4] + sSS32[tid * 4 + 1] + sSS32[tid * 4 + 2] + sSS32[tid * 4 + 3];
        const float inv = 1.f / (4.f * 50176.f);
        float m = S * inv;
        float ex2 = SS * inv;
        sMg[tid] = m;
        sRg[tid] = rsqrtf(ex2 - m * m + EPSV);
    }
    __syncthreads();
    if (tid < 32) {
        float mx = sS[tid] * (1.f / 50176.f);
        int g = tid >> 2;
        sF[tid] = (mx - sMg[g]) * sRg[g] * gnw[tid] + gnb[tid];
    }
    __syncthreads();
    if (tid == 0) {
        float mu = 0.f;
        for (int c = 0; c < 32; c++) mu += sF[c];
        mu *= (1.f / 32.f);
        float va = 0.f;
        for (int c = 0; c < 32; c++) { float d = sF[c] - mu; va = fmaf(d, d, va); }
        va *= (1.f / 32.f);
        float r = rsqrtf(va + EPSV);
        for (int c = 0; c < 32; c++) sFN[c] = (sF[c] - mu) * r * lnw[c] + lnb[c];
    }
    __syncthreads();
    for (int j = tid; j < NCLS; j += 1024) {
        float a = hb[j];
#pragma unroll
        for (int c = 0; c < 32; c++) a = fmaf(sFN[c], hw[c * NCLS + j], a);
        d_out[b * NCLS + j] = a;
    }
}

// ============================================================
extern "C" void kernel_launch(void* const* d_in, const int* in_sizes, int n_in,
                              void* d_out, int out_size) {
    const float* X        = (const float*)d_in[0];
    const float* stem_w   = (const float*)d_in[1];
    const float* bn_w     = (const float*)d_in[2];
    const float* bn_b     = (const float*)d_in[3];
    const float* gate_w   = (const float*)d_in[4];
    const float* gate_b   = (const float*)d_in[5];
    const float* expert_w = (const float*)d_in[6];
    const float* expert_b = (const float*)d_in[7];
    const float* gamma    = (const float*)d_in[8];
    const float* gn_w     = (const float*)d_in[9];
    const float* gn_b     = (const float*)d_in[10];
    const float* ln_w     = (const float*)d_in[11];
    const float* ln_b     = (const float*)d_in[12];
    const float* head_w   = (const float*)d_in[13];
    const float* head_b   = (const float*)d_in[14];
    float* out = (float*)d_out;

    k1_stem<<<NTOK, 256>>>(X, stem_w, bn_w, bn_b);
    k2_gate<<<(NTOK + 127) / 128, 128>>>(gate_w, gate_b);
    k3_dispatch<<<1, 512>>>(out);
    k4_expert<<<NTOK, 256>>>(expert_w, expert_b, gamma);
    k5_head<<<8, 1024>>>(gn_w, gn_b, ln_w, ln_b, head_w, head_b, out);
}

// round 8
// speedup vs baseline: 3.0446x; 1.8460x over previous
#include <cuda_runtime.h>
#include <math.h>

#define NTOK 1568
#define CH 32
#define NPIX 256
#define NEXP 8
#define CAPN 245
#define NCLS 1000
#define HWD 224
#define HP 14
#define EPSV 1e-5f
#define PI_F 3.14159265358979323846f

typedef unsigned long long u64;

// ---- scratch (no allocations allowed) ----
__device__ float g_tokens[NTOK * CH * NPIX];   // token layout (n,c,py,px)
__device__ float g_cmean[NTOK * CH];
__device__ int   g_top1[NTOK];
__device__ float g_ptop[NTOK];
__device__ float g_lse[NTOK];
__device__ float g_probs[NTOK * NEXP];
__device__ float g_wn[NTOK];
__device__ float g_psum[NTOK * CH];
__device__ float g_psumsq[NTOK * CH];
// mma A-fragments: [e][s(9)][mt(2)][kt(4)][lane(32)] float4  (288 KB)
__device__ __align__(16) float4 g_aw[NEXP * 9 * 2 * 4 * 32];

// ---- f32x2 helpers (used by K1) ----
__device__ __forceinline__ u64 pack2(float x, float y) {
    u64 r; asm("mov.b64 %0, {%1, %2};" : "=l"(r) : "f"(x), "f"(y)); return r;
}
__device__ __forceinline__ void unpack2(u64 v, float& x, float& y) {
    asm("mov.b64 {%0, %1}, %2;" : "=f"(x), "=f"(y) : "l"(v));
}
__device__ __forceinline__ u64 ffma2(u64 a, u64 b, u64 c) {
    u64 d; asm("fma.rn.f32x2 %0, %1, %2, %3;" : "=l"(d) : "l"(a), "l"(b), "l"(c));
    return d;
}

// ---- tf32 mma m16n8k8 (row.col) ----
__device__ __forceinline__ void mma_tf32(float4& d, const float4 a,
                                         unsigned b0, unsigned b1) {
    asm volatile(
        "mma.sync.aligned.m16n8k8.row.col.f32.tf32.tf32.f32 "
        "{%0,%1,%2,%3}, {%4,%5,%6,%7}, {%8,%9}, {%0,%1,%2,%3};\n"
        : "+f"(d.x), "+f"(d.y), "+f"(d.z), "+f"(d.w)
        : "r"(__float_as_uint(a.x)), "r"(__float_as_uint(a.y)),
          "r"(__float_as_uint(a.z)), "r"(__float_as_uint(a.w)),
          "r"(b0), "r"(b1));
}

// ============================================================
// K0: permute expert weights into mma A-fragment layout.
// a0=(gid,ctid) a1=(gid+8,ctid) a2=(gid,ctid+4) a3=(gid+8,ctid+4)
// over A[co=mt*16+...][ci=kt*8+...] = EW[((e*32+co)*32+ci)*9 + s]
// ============================================================
__global__ void __launch_bounds__(256)
k0_afrag(const float* __restrict__ EW) {
    int i = blockIdx.x * 256 + threadIdx.x;        // over 8*9*2*4*32 = 18432
    if (i >= NEXP * 9 * 2 * 4 * 32) return;
    int lane = i & 31;
    int kt = (i >> 5) & 3;
    int mt = (i >> 7) & 1;
    int r  = i >> 8;           // e*9 + s
    int s  = r % 9;
    int e  = r / 9;
    int gid = lane >> 2, ctid = lane & 3;
    int co0 = mt * 16 + gid, co1 = co0 + 8;
    int ci0 = kt * 8 + ctid, ci1 = ci0 + 4;
    float4 v;
    v.x = EW[((e * 32 + co0) * 32 + ci0) * 9 + s];
    v.y = EW[((e * 32 + co1) * 32 + ci0) * 9 + s];
    v.z = EW[((e * 32 + co0) * 32 + ci1) * 9 + s];
    v.w = EW[((e * 32 + co1) * 32 + ci1) * 9 + s];
    g_aw[i] = v;
}

// ============================================================
// K1: stem conv3x3 (3->32) + BN + SiLU -> tokens; fused channel means
// ============================================================
__global__ void __launch_bounds__(256)
k1_stem(const float* __restrict__ X, const float* __restrict__ W,
        const float* __restrict__ bnw, const float* __restrict__ bnb) {
    __shared__ __align__(16) float sIn[3 * 18 * 18];
    __shared__ __align__(16) float sW[32 * 28];
    __shared__ float sBw[32], sBb[32];
    __shared__ float sPart[8 * 32];
    int n = blockIdx.x;
    int b = n / 196, pr = (n % 196) / HP, pc = n % HP;
    int tid = threadIdx.x;

    for (int i = tid; i < 3 * 18 * 18; i += 256) {
        int ci = i / 324, r = (i % 324) / 18, c = i % 18;
        int gy = pr * 16 + r - 1, gx = pc * 16 + c - 1;
        float v = 0.f;
        if (gy >= 0 && gy < HWD && gx >= 0 && gx < HWD)
            v = X[((b * 3 + ci) * HWD + gy) * HWD + gx];
        sIn[i] = v;
    }
    for (int i = tid; i < 32 * 28; i += 256) {
        int co = i / 28, k = i % 28;
        sW[i] = (k < 27) ? W[co * 27 + k] : 0.f;
    }
    if (tid < 32) { sBw[tid] = bnw[tid]; sBb[tid] = bnb[tid]; }
    __syncthreads();

    int py = tid >> 4, px = tid & 15;
    float xin[28];
#pragma unroll
    for (int ci = 0; ci < 3; ci++)
#pragma unroll
        for (int dy = 0; dy < 3; dy++)
#pragma unroll
            for (int dx = 0; dx < 3; dx++)
                xin[ci * 9 + dy * 3 + dx] = sIn[ci * 324 + (py + dy) * 18 + (px + dx)];
    xin[27] = 0.f;
    u64 xp[14];
#pragma unroll
    for (int j = 0; j < 14; j++) xp[j] = pack2(xin[2 * j], xin[2 * j + 1]);

    int lane = tid & 31, wid = tid >> 5;
    for (int co = 0; co < 32; co++) {
        u64 acc = 0ULL;
#pragma unroll
        for (int j = 0; j < 14; j++)
            acc = ffma2(*(const u64*)(sW + co * 28 + 2 * j), xp[j], acc);
        float a0, a1; unpack2(acc, a0, a1);
        float a = a0 + a1;
        a = a * sBw[co] + sBb[co];
        float s = a / (1.f + __expf(-a));
        g_tokens[(n * CH + co) * NPIX + tid] = s;
        float ws = s;
#pragma unroll
        for (int off = 16; off > 0; off >>= 1)
            ws += __shfl_down_sync(0xffffffffu, ws, off);
        if (lane == 0) sPart[wid * 32 + co] = ws;
    }
    __syncthreads();
    if (tid < 32) {
        float sum = 0.f;
#pragma unroll
        for (int w = 0; w < 8; w++) sum += sPart[w * 32 + tid];
        g_cmean[n * CH + tid] = sum * (1.f / 256.f);
    }
}

// ============================================================
// K2: gate — one thread per token. 13 blocks x 128 threads.
// ============================================================
__global__ void __launch_bounds__(128)
k2_gate(const float* __restrict__ gate_w, const float* __restrict__ gate_b) {
    __shared__ float sGw[50 * 8];
    __shared__ float sGb[8];
    __shared__ float tab[14][9];
    int tid = threadIdx.x;

    for (int i = tid; i < 400; i += 128) sGw[i] = gate_w[i];
    if (tid < 8) sGb[tid] = gate_b[tid];
    if (tid < 56) {
        int b2 = tid >> 2, k = tid & 3;
        float f = (float)(1 << k) * PI_F;
        float ss = 0.f, cs = 0.f;
        for (int r = 0; r < 16; r++) {
            float ang = f * ((16.f * b2 + (float)r + 0.5f) / 224.f);
            ss += sinf(ang); cs += cosf(ang);
        }
        tab[b2][1 + 2 * k] = ss * (1.f / 16.f);
        tab[b2][2 + 2 * k] = cs * (1.f / 16.f);
    } else if (tid < 70) {
        int b2 = tid - 56;
        tab[b2][0] = (16.f * b2 + 8.f) / 224.f;
    }
    __syncthreads();

    int n = blockIdx.x * 128 + tid;
    if (n >= NTOK) return;
    int pr = (n % 196) / HP, pc = n % HP;

    float l[8];
#pragma unroll
    for (int e = 0; e < 8; e++) l[e] = sGb[e];
    const float4* cm4 = (const float4*)&g_cmean[n * CH];
#pragma unroll
    for (int i4 = 0; i4 < 8; i4++) {
        float4 v4 = cm4[i4];
        float vv[4] = {v4.x, v4.y, v4.z, v4.w};
#pragma unroll
        for (int q = 0; q < 4; q++) {
            int i = i4 * 4 + q;
#pragma unroll
            for (int e = 0; e < 8; e++) l[e] = fmaf(vv[q], sGw[i * 8 + e], l[e]);
        }
    }
    {
        float v0 = tab[pr][0], v1 = tab[pc][0];
#pragma unroll
        for (int e = 0; e < 8; e++) {
            l[e] = fmaf(v0, sGw[32 * 8 + e], l[e]);
            l[e] = fmaf(v1, sGw[33 * 8 + e], l[e]);
        }
    }
#pragma unroll
    for (int k = 0; k < 4; k++) {
#pragma unroll
        for (int sub = 0; sub < 4; sub++) {
            float v = (sub < 2) ? tab[pr][1 + 2 * k + sub] : tab[pc][1 + 2 * k + (sub - 2)];
#pragma unroll
            for (int e = 0; e < 8; e++)
                l[e] = fmaf(v, sGw[(34 + 4 * k + sub) * 8 + e], l[e]);
        }
    }
    float mx = l[0]; int am = 0;
#pragma unroll
    for (int e = 1; e < 8; e++) if (l[e] > mx) { mx = l[e]; am = e; }
    float pe[8], se = 0.f;
#pragma unroll
    for (int e = 0; e < 8; e++) { pe[e] = __expf(l[e] - mx); se += pe[e]; }
    float inv = 1.f / se;
#pragma unroll
    for (int e = 0; e < 8; e++) g_probs[n * 8 + e] = pe[e] * inv;
    g_top1[n] = am;
    g_ptop[n] = pe[am] * inv;
    g_lse[n] = mx + __logf(se);
}

// ============================================================
// K3: capacity scan (ballot, exact token order) + loss reductions
// ============================================================
__global__ void __launch_bounds__(512)
k3_dispatch(float* __restrict__ d_out) {
    __shared__ int   sT[NTOK];
    __shared__ float sWred[16][17];
    __shared__ int   sWC[16 * 9];
    __shared__ int   sRun[8];
    int tid = threadIdx.x;
    int lane = tid & 31, wid = tid >> 5;

    for (int i = tid; i < NTOK; i += 512) sT[i] = g_top1[i];
    if (tid < 8) sRun[tid] = 0;
    if (tid < 144) sWC[tid] = 0;
    __syncthreads();

    float part[17];
#pragma unroll
    for (int q = 0; q < 17; q++) part[q] = 0.f;
    for (int n = tid; n < NTOK; n += 512) {
        float lse = g_lse[n];
        part[0] += lse * lse;
        const float4* p4 = (const float4*)&g_probs[n * 8];
        float4 a = p4[0], b = p4[1];
        part[1] += a.x; part[2] += a.y; part[3] += a.z; part[4] += a.w;
        part[5] += b.x; part[6] += b.y; part[7] += b.z; part[8] += b.w;
        part[9 + sT[n]] += 1.f;
    }

    for (int c = 0; c < 4; c++) {
        int n = c * 512 + tid;
        bool act = n < NTOK;
        int e = act ? sT[n] : 8;
        unsigned m = __match_any_sync(0xffffffffu, e);
        int lr = __popc(m & ((1u << lane) - 1u));
        if (lr == 0) sWC[wid * 9 + e] = __popc(m);
        __syncthreads();
        if (act) {
            int base = sRun[e];
            for (int w2 = 0; w2 < wid; w2++) base += sWC[w2 * 9 + e];
            int rank = base + lr;
            g_wn[n] = (rank < CAPN) ? g_ptop[n] : 0.f;
        }
        int s = 0;
        if (tid < 8) for (int w2 = 0; w2 < 16; w2++) s += sWC[w2 * 9 + tid];
        __syncthreads();
        if (tid < 8) sRun[tid] += s;
        if (tid < 144) sWC[tid] = 0;
        __syncthreads();
    }

#pragma unroll
    for (int q = 0; q < 17; q++) {
#pragma unroll
        for (int off = 16; off > 0; off >>= 1)
            part[q] += __shfl_down_sync(0xffffffffu, part[q], off);
        if (lane == 0) sWred[wid][q] = part[q];
    }
    __syncthreads();
    if (tid == 0) {
        float res[17];
#pragma unroll
        for (int q = 0; q < 17; q++) {
            float s = 0.f;
            for (int w2 = 0; w2 < 16; w2++) s += sWred[w2][q];
            res[q] = s;
        }
        float z = res[0] / (float)NTOK;
        float imb = 0.f;
        for (int e = 0; e < 8; e++) imb += res[1 + e] * res[9 + e];
        imb *= (float)NEXP / ((float)NTOK * (float)NTOK);
        d_out[8000] = z;
        d_out[8001] = imb;
    }
}

// ============================================================
// K4: expert conv3x3 via 9-shift tf32 tensor-core GEMM.
// Image in padded smem (plane stride 328 -> conflict-free B frags).
// Warp w handles px [w*32, w*32+32) (rows 2w, 2w+1).
// ============================================================
#define PSTR 328   /* plane stride in floats; 328 % 32 == 8 */

__global__ void __launch_bounds__(256, 2)
k4_expert(const float* __restrict__ EB, const float* __restrict__ gamma) {
    __shared__ __align__(16) float sXp[CH * PSTR];   // [ci][18 rows x 18 cols @ stride 18]
    __shared__ float sPs[8][32], sPss[8][32];
    int n = blockIdx.x;
    int tid = threadIdx.x;
    float wn = g_wn[n];
    int e = g_top1[n];
    bool active = (wn != 0.f);
    int wid = tid >> 5, lane = tid & 31;
    int gid = lane >> 2, ctid = lane & 3;

    {
        u64* z = (u64*)sXp;
        for (int i = tid; i < CH * PSTR / 2; i += 256) z[i] = 0ULL;
    }
    __syncthreads();
    const float4* src = (const float4*)(g_tokens + (size_t)n * CH * NPIX);
    for (int i = tid; i < CH * NPIX / 4; i += 256) {
        float4 v = src[i];
        int c = i >> 6;
        int p = (i & 63) * 4;
        float* d = sXp + c * PSTR + ((p >> 4) + 1) * 18 + (p & 15) + 1;
        d[0] = v.x; d[1] = v.y; d[2] = v.z; d[3] = v.w;
    }
    __syncthreads();

    if (!active) {
        // dropped token: output = input; emit moments of t directly
        int row = lane >> 1, xb = (lane & 1) * 8;
#pragma unroll
        for (int c4 = 0; c4 < 4; c4++) {
            int co = wid * 4 + c4;
            const float* tp = sXp + co * PSTR + (row + 1) * 18 + xb + 1;
            float s = 0.f, ss = 0.f;
#pragma unroll
            for (int p = 0; p < 8; p++) { float v = tp[p]; s += v; ss = fmaf(v, v, ss); }
#pragma unroll
            for (int off = 16; off > 0; off >>= 1) {
                s  += __shfl_down_sync(0xffffffffu, s, off);
                ss += __shfl_down_sync(0xffffffffu, ss, off);
            }
            if (lane == 0) { g_psum[n * CH + co] = s; g_psumsq[n * CH + co] = ss; }
        }
        return;
    }

    float4 acc[2][4];
#pragma unroll
    for (int mt = 0; mt < 2; mt++)
#pragma unroll
        for (int nn = 0; nn < 4; nn++) acc[mt][nn] = make_float4(0.f, 0.f, 0.f, 0.f);

    // B-fragment base indices (floats) for this thread, per n-tile
    int bIdx[4];
#pragma unroll
    for (int nn = 0; nn < 4; nn++)
        bIdx[nn] = ctid * PSTR + (wid * 2 + (nn >> 1)) * 18 + (nn & 1) * 8 + gid;
    const unsigned* sU = (const unsigned*)sXp;
    const float4* aBase = g_aw + (size_t)e * 2304 + lane;

#pragma unroll
    for (int ky = 0; ky < 3; ky++) {
#pragma unroll
        for (int kx = 0; kx < 3; kx++) {
            const int s = ky * 3 + kx;
#pragma unroll
            for (int kt = 0; kt < 4; kt++) {
                const int off = kt * (8 * PSTR) + ky * 18 + kx;
                unsigned b0[4], b1[4];
#pragma unroll
                for (int nn = 0; nn < 4; nn++) {
                    b0[nn] = sU[bIdx[nn] + off];
                    b1[nn] = sU[bIdx[nn] + off + 4 * PSTR];
                }
#pragma unroll
                for (int mt = 0; mt < 2; mt++) {
                    float4 a = __ldg(aBase + ((s * 2 + mt) * 4 + kt) * 32);
#pragma unroll
                    for (int nn = 0; nn < 4; nn++)
                        mma_tf32(acc[mt][nn], a, b0[nn], b1[nn]);
                }
            }
        }
    }

    // epilogue: y = silu(D + b); v = t + gamma*wn*y; per-(warp,co) partial moments
#pragma unroll
    for (int mt = 0; mt < 2; mt++) {
#pragma unroll
        for (int half = 0; half < 2; half++) {
            int co = mt * 16 + gid + half * 8;
            float bco = __ldg(EB + e * CH + co);
            float gm = __ldg(gamma + co) * wn;
            float s = 0.f, ss = 0.f;
#pragma unroll
            for (int nn = 0; nn < 4; nn++) {
                float y0 = half ? acc[mt][nn].z : acc[mt][nn].x;
                float y1 = half ? acc[mt][nn].w : acc[mt][nn].y;
                int r = wid * 2 + (nn >> 1);
                int x = (nn & 1) * 8 + 2 * ctid;
                const float* tp = sXp + co * PSTR + (r + 1) * 18 + x + 1;
                float a0 = y0 + bco; a0 = a0 / (1.f + __expf(-a0));
                float a1 = y1 + bco; a1 = a1 / (1.f + __expf(-a1));
                float v0 = tp[0] + gm * a0;
                float v1 = tp[1] + gm * a1;
                s += v0 + v1;
                ss = fmaf(v0, v0, ss);
                ss = fmaf(v1, v1, ss);
            }
            // reduce over the 4-thread quad (ctid 0..3)
            s  += __shfl_xor_sync(0xffffffffu, s, 1);
            s  += __shfl_xor_sync(0xffffffffu, s, 2);
            ss += __shfl_xor_sync(0xffffffffu, ss, 1);
            ss += __shfl_xor_sync(0xffffffffu, ss, 2);
            if (ctid == 0) { sPs[wid][co] = s; sPss[wid][co] = ss; }
        }
    }
    __syncthreads();
    if (tid < 32) {
        float S = 0.f, SS = 0.f;
#pragma unroll
        for (int w = 0; w < 8; w++) { S += sPs[w][tid]; SS += sPss[w][tid]; }
        g_psum[n * CH + tid] = S;
        g_psumsq[n * CH + tid] = SS;
    }
}

// ============================================================
// K5: GroupNorm(from moments) + pool + LayerNorm + head
// ============================================================
__global__ void __launch_bounds__(1024)
k5_head(const float* __restrict__ gnw, const float* __restrict__ gnb,
        const float* __restrict__ lnw, const float* __restrict__ lnb,
        const float* __restrict__ hw, const float* __restrict__ hb,
        float* __restrict__ d_out) {
    __shared__ float sS32[32 * 32], sSS32[32 * 32];
    __shared__ float sS[32], sF[32], sFN[32];
    __shared__ float sMg[8], sRg[8];
    int b = blockIdx.x, tid = threadIdx.x;
    {
        int c = tid & 31, sl = tid >> 5;
        float S = 0.f, SS = 0.f;
        for (int t = sl; t < 196; t += 32) {
            int idx = (b * 196 + t) * CH + c;
            S += g_psum[idx]; SS += g_psumsq[idx];
        }
        sS32[sl * 32 + c] = S; sSS32[sl * 32 + c] = SS;
    }
    __syncthreads();
    if (tid < 32) {
        float S = 0.f, SS = 0.f;
#pragma unroll
        for (int sl = 0; sl < 32; sl++) { S += sS32[sl * 32 + tid]; SS += sSS32[sl * 32 + tid]; }
        sS[tid] = S; sS32[tid] = S; sSS32[tid] = SS;
    }
    __syncthreads();
    if (tid < 8) {
        float S  = sS32[tid * 4] + sS32[tid * 4 + 1] + sS32[tid * 4 + 2] + sS32[tid * 4 + 3];
        float SS = sSS32[tid * 4] + sSS32[tid * 4 + 1] + sSS32[tid * 4 + 2] + sSS32[tid * 4 + 3];
        const float inv = 1.f / (4.f * 50176.f);
        float m = S * inv;
        float ex2 = SS * inv;
        sMg[tid] = m;
        sRg[tid] = rsqrtf(ex2 - m * m + EPSV);
    }
    __syncthreads();
    if (tid < 32) {
        float mx = sS[tid] * (1.f / 50176.f);
        int g = tid >> 2;
        sF[tid] = (mx - sMg[g]) * sRg[g] * gnw[tid] + gnb[tid];
    }
    __syncthreads();
    if (tid == 0) {
        float mu = 0.f;
        for (int c = 0; c < 32; c++) mu += sF[c];
        mu *= (1.f / 32.f);
        float va = 0.f;
        for (int c = 0; c < 32; c++) { float d = sF[c] - mu; va = fmaf(d, d, va); }
        va *= (1.f / 32.f);
        float r = rsqrtf(va + EPSV);
        for (int c = 0; c < 32; c++) sFN[c] = (sF[c] - mu) * r * lnw[c] + lnb[c];
    }
    __syncthreads();
    for (int j = tid; j < NCLS; j += 1024) {
        float a = hb[j];
#pragma unroll
        for (int c = 0; c < 32; c++) a = fmaf(sFN[c], hw[c * NCLS + j], a);
        d_out[b * NCLS + j] = a;
    }
}

// ============================================================
extern "C" void kernel_launch(void* const* d_in, const int* in_sizes, int n_in,
                              void* d_out, int out_size) {
    const float* X        = (const float*)d_in[0];
    const float* stem_w   = (const float*)d_in[1];
    const float* bn_w     = (const float*)d_in[2];
    const float* bn_b     = (const float*)d_in[3];
    const float* gate_w   = (const float*)d_in[4];
    const float* gate_b   = (const float*)d_in[5];
    const float* expert_w = (const float*)d_in[6];
    const float* expert_b = (const float*)d_in[7];
    const float* gamma    = (const float*)d_in[8];
    const float* gn_w     = (const float*)d_in[9];
    const float* gn_b     = (const float*)d_in[10];
    const float* ln_w     = (const float*)d_in[11];
    const float* ln_b     = (const float*)d_in[12];
    const float* head_w   = (const float*)d_in[13];
    const float* head_b   = (const float*)d_in[14];
    float* out = (float*)d_out;

    k0_afrag<<<(NEXP * 9 * 2 * 4 * 32 + 255) / 256, 256>>>(expert_w);
    k1_stem<<<NTOK, 256>>>(X, stem_w, bn_w, bn_b);
    k2_gate<<<(NTOK + 127) / 128, 128>>>(gate_w, gate_b);
    k3_dispatch<<<1, 512>>>(out);
    k4_expert<<<NTOK, 256>>>(expert_b, gamma);
    k5_head<<<8, 1024>>>(gn_w, gn_b, ln_w, ln_b, head_w, head_b, out);
}